// round 3
// baseline (speedup 1.0000x reference)
#include <cuda_runtime.h>
#include <cuda_bf16.h>
#include <cstdint>
#include <cstddef>

// Problem constants
#define B_   32
#define C_   256
#define H_   56
#define W_   56
#define OC_  256
#define HID_ 65
#define K_   4
#define KS_  3
#define HW_  (H_*W_)                  // 3136
#define SPATIAL_OUT ((size_t)B_*OC_*H_*W_)   // 25,690,112
#define WELEM_PER_K (OC_*C_*KS_*KS_)  // 589,824
#define MCT_ (C_*KS_*KS_)             // 2304

// Scratch (device globals — no runtime allocation)
__device__ float g_pooled[B_*C_];
__device__ int   g_expert[B_];
__device__ float g_wq[K_*MCT_*OC_];   // layout [k][c*9+t][oc]  (oc fastest)

// ---------------------------------------------------------------------------
// 1) Global average pool: one block per (b,c)
// ---------------------------------------------------------------------------
__global__ void pool_kernel(const float* __restrict__ x) {
    int bc = blockIdx.x;                       // 0..B*C-1
    const float* p = x + (size_t)bc * HW_;
    float s = 0.f;
    for (int i = threadIdx.x; i < HW_; i += 256) s += p[i];
    #pragma unroll
    for (int o = 16; o; o >>= 1) s += __shfl_down_sync(0xffffffffu, s, o);
    __shared__ float sm[8];
    if ((threadIdx.x & 31) == 0) sm[threadIdx.x >> 5] = s;
    __syncthreads();
    if (threadIdx.x == 0) {
        float t = 0.f;
        #pragma unroll
        for (int i = 0; i < 8; i++) t += sm[i];
        g_pooled[bc] = t * (1.0f / (float)HW_);
    }
}

// ---------------------------------------------------------------------------
// 2) Attention MLP + argmax -> expert index, write raw logits
// ---------------------------------------------------------------------------
__global__ void attn_kernel(const float* __restrict__ w_fc1,
                            const float* __restrict__ w_fc2,
                            const float* __restrict__ b_fc2,
                            float* __restrict__ raw_out) {
    int b = blockIdx.x;
    __shared__ float ps[C_];
    __shared__ float hs[HID_];
    int tid = threadIdx.x;                     // 128 threads
    for (int i = tid; i < C_; i += 128) ps[i] = g_pooled[b*C_ + i];
    __syncthreads();
    if (tid < HID_) {
        const float* w = w_fc1 + tid * C_;
        float s = 0.f;
        for (int c = 0; c < C_; c++) s = fmaf(ps[c], w[c], s);
        hs[tid] = fmaxf(s, 0.f);
    }
    __syncthreads();
    if (tid == 0) {
        int best = 0; float bv = -3.4e38f;
        for (int k = 0; k < K_; k++) {
            const float* w = w_fc2 + k * HID_;
            float s = b_fc2[k];
            for (int j = 0; j < HID_; j++) s = fmaf(hs[j], w[j], s);
            raw_out[b*K_ + k] = s;
            if (s > bv) { bv = s; best = k; }   // strict '>' = first-max, matches argmax
        }
        g_expert[b] = best;
    }
}

// ---------------------------------------------------------------------------
// 3) LSQ quantize + transpose to [k][c*9+t][oc]
//    jnp.round = round-half-even = rintf (default RN mode)
// ---------------------------------------------------------------------------
__global__ void quant_kernel(const float* __restrict__ weight,
                             const float* __restrict__ alpha) {
    int idx = blockIdx.x * 256 + threadIdx.x;
    if (idx >= K_ * WELEM_PER_K) return;
    int k   = idx / WELEM_PER_K;
    int rem = idx - k * WELEM_PER_K;           // = oc*2304 + (c*9+t)
    int oc  = rem / MCT_;
    int m   = rem - oc * MCT_;                 // c*9+t
    float a = alpha[k];
    float d = weight[idx] / a;
    if (rem == 0) {                            // only flat element [k,0] is clamped
        if      (k == 0) d = fminf(fmaxf(d, -2.f), 1.f);
        else if (k == 1) d = fminf(fmaxf(d, -4.f), 3.f);
        else if (k == 2) d = fminf(fmaxf(d, -8.f), 7.f);
    }
    g_wq[((size_t)k * MCT_ + m) * OC_ + oc] = rintf(d) * a;
}

// ---------------------------------------------------------------------------
// 4) Per-sample 3x3 conv with the selected expert weight.
//    Block tile: 128 oc x (8 rows x 16 cols). Thread tile: 8 oc x 8 rows x 1 col.
//    C processed in chunks of 8 through shared memory.
// ---------------------------------------------------------------------------
__global__ __launch_bounds__(256, 2)
void conv_kernel(const float* __restrict__ x,
                 const float* __restrict__ bias_w,
                 float* __restrict__ out) {
    __shared__ float xs[8][10][18];            // [c'][iy][ix] halo'd x tile
    __shared__ float ws[72][128];              // [c'*9+t][oc']

    const int b    = blockIdx.z;
    const int ocb  = blockIdx.y;               // 0..1
    const int rowt = blockIdx.x >> 2;          // 0..6
    const int colt = blockIdx.x & 3;           // 0..3
    const int row0 = rowt * 8, col0 = colt * 16;
    const int tid  = threadIdx.x;
    const int r    = tid >> 4;                 // 0..15 (oc group)
    const int cc   = tid & 15;                 // 0..15 (pixel column)
    const int e    = g_expert[b];

    const float* xb    = x + (size_t)b * C_ * HW_;
    const float* wbase = g_wq + ((size_t)e * MCT_) * OC_ + ocb * 128;

    float acc[8][8];
    #pragma unroll
    for (int i = 0; i < 8; i++)
        #pragma unroll
        for (int j = 0; j < 8; j++) acc[i][j] = 0.f;

    #pragma unroll 1
    for (int cb = 0; cb < C_ / 8; cb++) {
        __syncthreads();
        // weights: 72 rows x 128 oc = 9216 floats, coalesced 512B rows
        #pragma unroll
        for (int i = 0; i < 36; i++) {
            int idx = tid + i * 256;
            int o = idx & 127, j = idx >> 7;   // j in 0..71
            ws[j][o] = wbase[(size_t)(cb * 72 + j) * OC_ + o];
        }
        // x tile with halo: 8ch x 10 x 18 = 1440 floats, zero-padded at borders
        for (int i = tid; i < 1440; i += 256) {
            int c  = i / 180, rem2 = i - c * 180;
            int iy = rem2 / 18, ix = rem2 - iy * 18;
            int gy = row0 - 1 + iy, gx = col0 - 1 + ix;
            float v = 0.f;
            if ((unsigned)gy < (unsigned)H_ && (unsigned)gx < (unsigned)W_)
                v = xb[(size_t)(cb * 8 + c) * HW_ + gy * W_ + gx];
            xs[c][iy][ix] = v;
        }
        __syncthreads();

        #pragma unroll 2
        for (int c = 0; c < 8; c++) {
            #pragma unroll
            for (int dy = 0; dy < 3; dy++) {
                #pragma unroll
                for (int dx = 0; dx < 3; dx++) {
                    const float* wp = &ws[c * 9 + dy * 3 + dx][r * 8];
                    float4 w0 = *reinterpret_cast<const float4*>(wp);
                    float4 w1 = *reinterpret_cast<const float4*>(wp + 4);
                    float wr[8] = {w0.x, w0.y, w0.z, w0.w, w1.x, w1.y, w1.z, w1.w};
                    float xr[8];
                    #pragma unroll
                    for (int py = 0; py < 8; py++) xr[py] = xs[c][py + dy][cc + dx];
                    #pragma unroll
                    for (int oo = 0; oo < 8; oo++)
                        #pragma unroll
                        for (int py = 0; py < 8; py++)
                            acc[oo][py] = fmaf(wr[oo], xr[py], acc[oo][py]);
                }
            }
        }
    }

    const int gx = col0 + cc;
    if (gx < W_) {
        const int oc0 = ocb * 128 + r * 8;
        #pragma unroll
        for (int oo = 0; oo < 8; oo++) {
            float bv = bias_w[e * OC_ + oc0 + oo];
            float* op = out + ((size_t)(b * OC_ + oc0 + oo) * H_ + row0) * W_ + gx;
            #pragma unroll
            for (int py = 0; py < 8; py++)
                op[py * W_] = acc[oo][py] + bv;
        }
    }
}

// ---------------------------------------------------------------------------
extern "C" void kernel_launch(void* const* d_in, const int* in_sizes, int n_in,
                              void* d_out, int out_size) {
    const float* x      = (const float*)d_in[0];   // (32,256,56,56)
    const float* w_fc1  = (const float*)d_in[1];   // (65,256)
    const float* w_fc2  = (const float*)d_in[2];   // (4,65)
    const float* b_fc2  = (const float*)d_in[3];   // (4,)
    const float* alpha  = (const float*)d_in[4];   // (4,1)
    const float* weight = (const float*)d_in[5];   // (4,256,256,3,3)
    const float* bias_w = (const float*)d_in[6];   // (4,256)
    float* out = (float*)d_out;

    // raw logits go after the conv output (tuple flattened in order)
    float* raw_out = out + SPATIAL_OUT;

    pool_kernel<<<B_ * C_, 256>>>(x);
    attn_kernel<<<B_, 128>>>(w_fc1, w_fc2, b_fc2, raw_out);
    quant_kernel<<<(K_ * WELEM_PER_K + 255) / 256, 256>>>(weight, alpha);

    dim3 grid(28 /*7 row-tiles x 4 col-tiles*/, 2 /*oc halves*/, B_);
    conv_kernel<<<grid, 256>>>(x, bias_w, out);
}

// round 5
// speedup vs baseline: 3.1053x; 3.1053x over previous
#include <cuda_runtime.h>
#include <cuda_bf16.h>
#include <cstdint>
#include <cstddef>

// ---------------- problem constants ----------------
#define B_   32
#define C_   256
#define H_   56
#define W_   56
#define OC_  256
#define HID_ 65
#define K_   4
#define HW_  3136
#define HP_  58                         // padded spatial (56+2)
#define KDIM 2304                       // 9 taps * 256 ch
#define SPATIAL_OUT ((size_t)B_*OC_*H_*W_)
#define NTILE 25                        // ceil(3136/128) pixel tiles

// ---------------- device scratch (no runtime allocation) ----------------
__device__ float g_pooled[B_*C_];
__device__ int   g_expert[B_];
__device__ __align__(16) __nv_bfloat16 g_wA[(size_t)K_*OC_*KDIM];    // [e][oc][t*256+c] int values
__device__ __align__(16) __nv_bfloat16 g_xhi[(size_t)B_*HP_*HP_*C_]; // [b][py][px][c]
__device__ __align__(16) __nv_bfloat16 g_xlo[(size_t)B_*HP_*HP_*C_];

// ---------------- PTX helpers (arch-agnostic: sm_80+) ----------------
__device__ __forceinline__ uint32_t s2u(const void* p) {
    uint32_t a;
    asm("{ .reg .u64 t; cvta.to.shared.u64 t, %1; cvt.u32.u64 %0, t; }" : "=r"(a) : "l"(p));
    return a;
}
__device__ __forceinline__ void cpa16(uint32_t saddr, const void* g) {
    asm volatile("cp.async.ca.shared.global [%0], [%1], 16;" :: "r"(saddr), "l"(g) : "memory");
}
__device__ __forceinline__ void cpa_commit() {
    asm volatile("cp.async.commit_group;" ::: "memory");
}
template<int N>
__device__ __forceinline__ void cpa_wait() {
    asm volatile("cp.async.wait_group %0;" :: "n"(N) : "memory");
}
__device__ __forceinline__ void ldm_x4(uint32_t& r0, uint32_t& r1, uint32_t& r2, uint32_t& r3,
                                       uint32_t a) {
    asm volatile("ldmatrix.sync.aligned.m8n8.x4.shared.b16 {%0,%1,%2,%3}, [%4];"
                 : "=r"(r0), "=r"(r1), "=r"(r2), "=r"(r3) : "r"(a));
}
__device__ __forceinline__ void mma16816(float* d, const uint32_t* a, const uint32_t* b) {
    asm volatile("mma.sync.aligned.m16n8k16.row.col.f32.bf16.bf16.f32 "
                 "{%0,%1,%2,%3},{%4,%5,%6,%7},{%8,%9},{%0,%1,%2,%3};"
                 : "+f"(d[0]), "+f"(d[1]), "+f"(d[2]), "+f"(d[3])
                 : "r"(a[0]), "r"(a[1]), "r"(a[2]), "r"(a[3]), "r"(b[0]), "r"(b[1]));
}

// ---------------------------------------------------------------------------
// 1) Global average pool
// ---------------------------------------------------------------------------
__global__ void pool_kernel(const float* __restrict__ x) {
    int bc = blockIdx.x;
    const float* p = x + (size_t)bc * HW_;
    float s = 0.f;
    for (int i = threadIdx.x; i < HW_; i += 256) s += p[i];
    #pragma unroll
    for (int o = 16; o; o >>= 1) s += __shfl_down_sync(0xffffffffu, s, o);
    __shared__ float sm[8];
    if ((threadIdx.x & 31) == 0) sm[threadIdx.x >> 5] = s;
    __syncthreads();
    if (threadIdx.x == 0) {
        float t = 0.f;
        #pragma unroll
        for (int i = 0; i < 8; i++) t += sm[i];
        g_pooled[bc] = t * (1.0f / (float)HW_);
    }
}

// ---------------------------------------------------------------------------
// 2) Attention MLP + argmax expert select + raw logits
// ---------------------------------------------------------------------------
__global__ void attn_kernel(const float* __restrict__ w_fc1,
                            const float* __restrict__ w_fc2,
                            const float* __restrict__ b_fc2,
                            float* __restrict__ raw_out) {
    int b = blockIdx.x;
    __shared__ float ps[C_];
    __shared__ float hs[HID_];
    int tid = threadIdx.x;
    for (int i = tid; i < C_; i += 128) ps[i] = g_pooled[b*C_ + i];
    __syncthreads();
    if (tid < HID_) {
        const float* w = w_fc1 + tid * C_;
        float s = 0.f;
        for (int c = 0; c < C_; c++) s = fmaf(ps[c], w[c], s);
        hs[tid] = fmaxf(s, 0.f);
    }
    __syncthreads();
    if (tid == 0) {
        int best = 0; float bv = -3.4e38f;
        for (int k = 0; k < K_; k++) {
            const float* w = w_fc2 + k * HID_;
            float s = b_fc2[k];
            for (int j = 0; j < HID_; j++) s = fmaf(hs[j], w[j], s);
            raw_out[b*K_ + k] = s;
            if (s > bv) { bv = s; best = k; }
        }
        g_expert[b] = best;
    }
}

// ---------------------------------------------------------------------------
// 3) Quantize weights -> integer bf16, layout [e][oc][t*256+c]
//    (alpha applied in epilogue; jnp.round = round-half-even = rintf)
// ---------------------------------------------------------------------------
__global__ void quantw_kernel(const float* __restrict__ w,
                              const float* __restrict__ alpha) {
    int idx = blockIdx.x * 256 + threadIdx.x;
    if (idx >= K_ * OC_ * C_ * 9) return;
    int k   = idx / (OC_ * C_ * 9);
    int rem = idx - k * (OC_ * C_ * 9);      // oc*2304 + c*9 + t
    int oc  = rem / (C_ * 9);
    int r2  = rem - oc * (C_ * 9);
    int c   = r2 / 9, t = r2 - c * 9;
    float d = w[idx] / alpha[k];
    if (rem == 0) {
        if      (k == 0) d = fminf(fmaxf(d, -2.f), 1.f);
        else if (k == 1) d = fminf(fmaxf(d, -4.f), 3.f);
        else if (k == 2) d = fminf(fmaxf(d, -8.f), 7.f);
    }
    g_wA[((size_t)k * OC_ + oc) * KDIM + t * C_ + c] = __float2bfloat16(rintf(d));
}

// ---------------------------------------------------------------------------
// 4a) Zero the padded borders of g_xhi/g_xlo
// ---------------------------------------------------------------------------
__global__ void zpad_kernel() {
    int b = blockIdx.y, i = blockIdx.x;        // i in 0..227
    int py, px;
    if      (i < 58)  { py = 0;          px = i;       }
    else if (i < 116) { py = 57;         px = i - 58;  }
    else if (i < 172) { py = i - 115;    px = 0;       }
    else              { py = i - 171;    px = 57;      }
    size_t off = (((size_t)b * HP_ + py) * HP_ + px) * C_ + threadIdx.x;
    g_xhi[off] = __float2bfloat16(0.f);
    g_xlo[off] = __float2bfloat16(0.f);
}

// ---------------------------------------------------------------------------
// 4b) Transpose x -> padded [b][py][px][c] bf16 hi/lo split
// ---------------------------------------------------------------------------
__global__ void xprep_kernel(const float* __restrict__ x) {
    __shared__ float sm[64 * 57];              // [c][px] padded stride
    int b = blockIdx.y, y = blockIdx.x;
    int tid = threadIdx.x;
    for (int cb = 0; cb < 4; cb++) {
        __syncthreads();
        for (int idx = tid; idx < 64 * 56; idx += 256) {
            int i = idx / 56, j = idx - i * 56;
            sm[i * 57 + j] = x[((size_t)(b * C_ + cb * 64 + i)) * HW_ + y * W_ + j];
        }
        __syncthreads();
        for (int idx = tid; idx < 64 * 56; idx += 256) {
            int c = idx & 63, p = idx >> 6;
            float v = sm[c * 57 + p];
            __nv_bfloat16 h = __float2bfloat16(v);
            __nv_bfloat16 l = __float2bfloat16(v - __bfloat162float(h));
            size_t off = (((size_t)b * HP_ + (y + 1)) * HP_ + (p + 1)) * C_ + cb * 64 + c;
            g_xhi[off] = h;
            g_xlo[off] = l;
        }
    }
}

// ---------------------------------------------------------------------------
// 5) mma.sync implicit-GEMM conv.
//    CTA: 128 oc x 128 px.  K = 72 chunks of 64 (9 taps x 4 ch-blocks x {hi,lo}).
//    8 warps as 2(M) x 4(N); warp tile 64 oc x 32 px; double-buffered cp.async.
// ---------------------------------------------------------------------------
#define CHUNK_BYTES 32768                      // A 16K + B 16K per buffer
#define SMEM_CONV   (2 * CHUNK_BYTES)          // 64 KB

__global__ void __launch_bounds__(256, 2)
conv_kernel(const float* __restrict__ bias_w,
            const float* __restrict__ alpha,
            float* __restrict__ out) {
    extern __shared__ __align__(16) char smem[];
    const uint32_t sbase = s2u(smem);
    const int tid  = threadIdx.x;
    const int lane = tid & 31, wid = tid >> 5;
    const int wm   = wid & 1;                  // M half (64 oc)
    const int wn   = wid >> 1;                 // N quarter (32 px)
    const int tile0 = blockIdx.x * 128;
    const int ocb  = blockIdx.y;
    const int b    = blockIdx.z;
    const int e    = g_expert[b];

    // ---- loader addressing (fixed per thread) ----
    const int lrow = tid >> 1;                 // 0..127 (row of A and of B)
    const int lu0  = (tid & 1) * 4;            // first of 4 uint4 slots
    int pix = tile0 + lrow; if (pix > HW_ - 1) pix = HW_ - 1;
    int py = pix / W_, px = pix - py * W_;
    const __nv_bfloat16* gA_row = g_wA + ((size_t)(e * OC_ + ocb * 128 + lrow)) * KDIM;
    const size_t xoff = (((size_t)b * HP_ + py) * HP_ + px) * C_;
    const uint32_t sA_row = sbase + lrow * 128;
    const uint32_t sB_row = sbase + 16384 + lrow * 128;
    const int swz = (lrow & 7);

    #define LOAD_CHUNK(CH, D) do {                                              \
        int _s = (CH) >= 36, _r = _s ? (CH) - 36 : (CH);                        \
        int _t = _r >> 2, _q = _r & 3;                                          \
        const uint4* _ga = (const uint4*)(gA_row + _t * C_ + _q * 64);          \
        const __nv_bfloat16* _gx = (_s ? g_xlo : g_xhi) + xoff                  \
                                 + ((_t / 3) * HP_ + (_t % 3)) * C_ + _q * 64;  \
        const uint4* _gb = (const uint4*)_gx;                                   \
        uint32_t _ao = sA_row + (D) * CHUNK_BYTES;                              \
        uint32_t _bo = sB_row + (D) * CHUNK_BYTES;                              \
        _Pragma("unroll")                                                       \
        for (int _u = lu0; _u < lu0 + 4; _u++) {                                \
            cpa16(_ao + (uint32_t)((_u ^ swz) << 4), _ga + _u);                 \
            cpa16(_bo + (uint32_t)((_u ^ swz) << 4), _gb + _u);                 \
        }                                                                        \
    } while (0)

    float acc[4][4][4];
    #pragma unroll
    for (int i = 0; i < 4; i++)
        #pragma unroll
        for (int j = 0; j < 4; j++)
            #pragma unroll
            for (int f = 0; f < 4; f++) acc[i][j][f] = 0.f;

    // ---- ldmatrix lane addressing (fixed per thread) ----
    // A tiles order: [m0-7,k0-7],[m8-15,k0-7],[m0-7,k8-15],[m8-15,k8-15]
    const int a_r  = (lane & 7) + ((lane >> 3) & 1) * 8;   // row within 16
    const int a_kb = (lane >> 4) * 16;                     // byte offset within k16
    // B tiles order: [n0-7,k0-7],[n0-7,k8-15],[n8-15,k0-7],[n8-15,k8-15]
    const int b_r  = (lane & 7) + (lane >> 4) * 8;
    const int b_kb = ((lane >> 3) & 1) * 16;

    LOAD_CHUNK(0, 0);
    cpa_commit();

    int buf = 0;
    #pragma unroll 1
    for (int ch = 0; ch < 72; ch++) {
        if (ch < 71) { LOAD_CHUNK(ch + 1, buf ^ 1); cpa_commit(); cpa_wait<1>(); }
        else         { cpa_wait<0>(); }
        __syncthreads();

        const uint32_t sA = sbase + buf * CHUNK_BYTES;
        const uint32_t sB = sA + 16384;
        #pragma unroll
        for (int kk = 0; kk < 4; kk++) {
            uint32_t a[4][4];
            #pragma unroll
            for (int mi = 0; mi < 4; mi++) {
                int row = wm * 64 + mi * 16 + a_r;
                int kb  = kk * 32 + a_kb;
                ldm_x4(a[mi][0], a[mi][1], a[mi][2], a[mi][3],
                       sA + row * 128 + (kb ^ ((row & 7) << 4)));
            }
            #pragma unroll
            for (int pr = 0; pr < 2; pr++) {
                uint32_t bb[4];
                int nrow = wn * 32 + pr * 16 + b_r;
                int kb   = kk * 32 + b_kb;
                ldm_x4(bb[0], bb[1], bb[2], bb[3],
                       sB + nrow * 128 + (kb ^ ((nrow & 7) << 4)));
                #pragma unroll
                for (int mi = 0; mi < 4; mi++) {
                    mma16816(acc[mi][pr * 2],     a[mi], bb);
                    mma16816(acc[mi][pr * 2 + 1], a[mi], bb + 2);
                }
            }
        }
        __syncthreads();
        buf ^= 1;
    }

    // ---- epilogue: alpha * acc + bias, direct float2 stores ----
    const float al = alpha[e];
    const int qn = lane & 3, qm = lane >> 2;
    #pragma unroll
    for (int mi = 0; mi < 4; mi++) {
        int oc0 = ocb * 128 + wm * 64 + mi * 16 + qm;
        float bv0 = bias_w[e * OC_ + oc0];
        float bv1 = bias_w[e * OC_ + oc0 + 8];
        #pragma unroll
        for (int ni = 0; ni < 4; ni++) {
            int p = tile0 + wn * 32 + ni * 8 + qn * 2;
            if (p < HW_) {
                float2 v0, v1;
                v0.x = acc[mi][ni][0] * al + bv0;
                v0.y = acc[mi][ni][1] * al + bv0;
                v1.x = acc[mi][ni][2] * al + bv1;
                v1.y = acc[mi][ni][3] * al + bv1;
                *(float2*)(out + ((size_t)(b * OC_ + oc0)) * HW_ + p)     = v0;
                *(float2*)(out + ((size_t)(b * OC_ + oc0 + 8)) * HW_ + p) = v1;
            }
        }
    }
}

// ---------------------------------------------------------------------------
extern "C" void kernel_launch(void* const* d_in, const int* in_sizes, int n_in,
                              void* d_out, int out_size) {
    const float* x      = (const float*)d_in[0];
    const float* w_fc1  = (const float*)d_in[1];
    const float* w_fc2  = (const float*)d_in[2];
    const float* b_fc2  = (const float*)d_in[3];
    const float* alpha  = (const float*)d_in[4];
    const float* weight = (const float*)d_in[5];
    const float* bias_w = (const float*)d_in[6];
    float* out = (float*)d_out;
    float* raw_out = out + SPATIAL_OUT;

    pool_kernel<<<B_ * C_, 256>>>(x);
    attn_kernel<<<B_, 128>>>(w_fc1, w_fc2, b_fc2, raw_out);
    quantw_kernel<<<(K_ * OC_ * C_ * 9 + 255) / 256, 256>>>(weight, alpha);
    zpad_kernel<<<dim3(228, B_), 256>>>();
    xprep_kernel<<<dim3(H_, B_), 256>>>(x);

    cudaFuncSetAttribute(conv_kernel, cudaFuncAttributeMaxDynamicSharedMemorySize, SMEM_CONV);
    conv_kernel<<<dim3(NTILE, 2, B_), 256, SMEM_CONV>>>(bias_w, alpha, out);
}

// round 6
// speedup vs baseline: 5.0414x; 1.6235x over previous
#include <cuda_runtime.h>
#include <cuda_bf16.h>
#include <cuda_fp16.h>
#include <cstdint>
#include <cstddef>

// ---------------- problem constants ----------------
#define B_   32
#define C_   256
#define H_   56
#define W_   56
#define OC_  256
#define HID_ 65
#define K_   4
#define HW_  3136
#define HP_  58                         // padded spatial (56+2)
#define KDIM 2304                       // 9 taps * 256 ch
#define SPATIAL_OUT ((size_t)B_*OC_*H_*W_)
#define NTILE 25                        // ceil(3136/128) pixel tiles

// ---------------- device scratch (no runtime allocation) ----------------
__device__ float g_pooled[B_*C_];
__device__ int   g_expert[B_];
__device__ __align__(16) __half g_wA[(size_t)K_*OC_*KDIM];    // [e][oc][t*256+c] integer values
__device__ __align__(16) __half g_xh[(size_t)B_*HP_*HP_*C_];  // [b][py][px][c] fp16

// ---------------- PTX helpers (arch-agnostic: sm_80+) ----------------
__device__ __forceinline__ uint32_t s2u(const void* p) {
    uint32_t a;
    asm("{ .reg .u64 t; cvta.to.shared.u64 t, %1; cvt.u32.u64 %0, t; }" : "=r"(a) : "l"(p));
    return a;
}
__device__ __forceinline__ void cpa16(uint32_t saddr, const void* g) {
    asm volatile("cp.async.ca.shared.global [%0], [%1], 16;" :: "r"(saddr), "l"(g) : "memory");
}
__device__ __forceinline__ void cpa_commit() {
    asm volatile("cp.async.commit_group;" ::: "memory");
}
template<int N>
__device__ __forceinline__ void cpa_wait() {
    asm volatile("cp.async.wait_group %0;" :: "n"(N) : "memory");
}
__device__ __forceinline__ void ldm_x4(uint32_t& r0, uint32_t& r1, uint32_t& r2, uint32_t& r3,
                                       uint32_t a) {
    asm volatile("ldmatrix.sync.aligned.m8n8.x4.shared.b16 {%0,%1,%2,%3}, [%4];"
                 : "=r"(r0), "=r"(r1), "=r"(r2), "=r"(r3) : "r"(a));
}
__device__ __forceinline__ void mma16816(float* d, const uint32_t* a, const uint32_t* b) {
    asm volatile("mma.sync.aligned.m16n8k16.row.col.f32.f16.f16.f32 "
                 "{%0,%1,%2,%3},{%4,%5,%6,%7},{%8,%9},{%0,%1,%2,%3};"
                 : "+f"(d[0]), "+f"(d[1]), "+f"(d[2]), "+f"(d[3])
                 : "r"(a[0]), "r"(a[1]), "r"(a[2]), "r"(a[3]), "r"(b[0]), "r"(b[1]));
}

// ---------------------------------------------------------------------------
// 1) Global average pool
// ---------------------------------------------------------------------------
__global__ void pool_kernel(const float* __restrict__ x) {
    int bc = blockIdx.x;
    const float* p = x + (size_t)bc * HW_;
    float s = 0.f;
    for (int i = threadIdx.x; i < HW_; i += 256) s += p[i];
    #pragma unroll
    for (int o = 16; o; o >>= 1) s += __shfl_down_sync(0xffffffffu, s, o);
    __shared__ float sm[8];
    if ((threadIdx.x & 31) == 0) sm[threadIdx.x >> 5] = s;
    __syncthreads();
    if (threadIdx.x == 0) {
        float t = 0.f;
        #pragma unroll
        for (int i = 0; i < 8; i++) t += sm[i];
        g_pooled[bc] = t * (1.0f / (float)HW_);
    }
}

// ---------------------------------------------------------------------------
// 2) Attention MLP + argmax expert select + raw logits
// ---------------------------------------------------------------------------
__global__ void attn_kernel(const float* __restrict__ w_fc1,
                            const float* __restrict__ w_fc2,
                            const float* __restrict__ b_fc2,
                            float* __restrict__ raw_out) {
    int b = blockIdx.x;
    __shared__ float ps[C_];
    __shared__ float hs[HID_];
    int tid = threadIdx.x;
    for (int i = tid; i < C_; i += 128) ps[i] = g_pooled[b*C_ + i];
    __syncthreads();
    if (tid < HID_) {
        const float* w = w_fc1 + tid * C_;
        float s = 0.f;
        for (int c = 0; c < C_; c++) s = fmaf(ps[c], w[c], s);
        hs[tid] = fmaxf(s, 0.f);
    }
    __syncthreads();
    if (tid == 0) {
        int best = 0; float bv = -3.4e38f;
        for (int k = 0; k < K_; k++) {
            const float* w = w_fc2 + k * HID_;
            float s = b_fc2[k];
            for (int j = 0; j < HID_; j++) s = fmaf(hs[j], w[j], s);
            raw_out[b*K_ + k] = s;
            if (s > bv) { bv = s; best = k; }
        }
        g_expert[b] = best;
    }
}

// ---------------------------------------------------------------------------
// 3) Quantize weights -> integer fp16, layout [e][oc][t*256+c]
//    (alpha applied in epilogue; jnp.round = round-half-even = rintf)
// ---------------------------------------------------------------------------
__global__ void quantw_kernel(const float* __restrict__ w,
                              const float* __restrict__ alpha) {
    int idx = blockIdx.x * 256 + threadIdx.x;
    if (idx >= K_ * OC_ * C_ * 9) return;
    int k   = idx / (OC_ * C_ * 9);
    int rem = idx - k * (OC_ * C_ * 9);      // oc*2304 + c*9 + t
    int oc  = rem / (C_ * 9);
    int r2  = rem - oc * (C_ * 9);
    int c   = r2 / 9, t = r2 - c * 9;
    float d = w[idx] / alpha[k];
    if (rem == 0) {
        if      (k == 0) d = fminf(fmaxf(d, -2.f), 1.f);
        else if (k == 1) d = fminf(fmaxf(d, -4.f), 3.f);
        else if (k == 2) d = fminf(fmaxf(d, -8.f), 7.f);
    }
    g_wA[((size_t)k * OC_ + oc) * KDIM + t * C_ + c] = __float2half(rintf(d));
}

// ---------------------------------------------------------------------------
// 4a) Zero the padded borders of g_xh
// ---------------------------------------------------------------------------
__global__ void zpad_kernel() {
    int b = blockIdx.y, i = blockIdx.x;        // i in 0..227
    int py, px;
    if      (i < 58)  { py = 0;          px = i;       }
    else if (i < 116) { py = 57;         px = i - 58;  }
    else if (i < 172) { py = i - 115;    px = 0;       }
    else              { py = i - 171;    px = 57;      }
    g_xh[(((size_t)b * HP_ + py) * HP_ + px) * C_ + threadIdx.x] = __float2half(0.f);
}

// ---------------------------------------------------------------------------
// 4b) Transpose x -> padded [b][py][px][c] fp16
// ---------------------------------------------------------------------------
__global__ void xprep_kernel(const float* __restrict__ x) {
    __shared__ float sm[64 * 57];              // [c][px] padded stride
    int b = blockIdx.y, y = blockIdx.x;
    int tid = threadIdx.x;
    for (int cb = 0; cb < 4; cb++) {
        __syncthreads();
        for (int idx = tid; idx < 64 * 56; idx += 256) {
            int i = idx / 56, j = idx - i * 56;
            sm[i * 57 + j] = x[((size_t)(b * C_ + cb * 64 + i)) * HW_ + y * W_ + j];
        }
        __syncthreads();
        for (int idx = tid; idx < 64 * 56; idx += 256) {
            int c = idx & 63, p = idx >> 6;
            g_xh[(((size_t)b * HP_ + (y + 1)) * HP_ + (p + 1)) * C_ + cb * 64 + c] =
                __float2half(sm[c * 57 + p]);
        }
    }
}

// ---------------------------------------------------------------------------
// 5) mma.sync implicit-GEMM conv (fp16 operands, fp32 accumulate).
//    CTA: 128 oc x 128 px.  K = 36 chunks of 64 (9 taps x 4 ch-blocks).
//    8 warps as 2(M) x 4(N); warp tile 64 oc x 32 px; 3-stage cp.async ring.
// ---------------------------------------------------------------------------
#define CHUNK_BYTES 32768                      // A 16K + B 16K per stage
#define NSTAGE 3
#define SMEM_CONV (NSTAGE * CHUNK_BYTES)       // 96 KB
#define NCHUNK 36

__global__ void __launch_bounds__(256, 2)
conv_kernel(const float* __restrict__ bias_w,
            const float* __restrict__ alpha,
            float* __restrict__ out) {
    extern __shared__ __align__(16) char smem[];
    const uint32_t sbase = s2u(smem);
    const int tid  = threadIdx.x;
    const int lane = tid & 31, wid = tid >> 5;
    const int wm   = wid & 1;                  // M half (64 oc)
    const int wn   = wid >> 1;                 // N quarter (32 px)
    const int tile0 = blockIdx.x * 128;
    const int ocb  = blockIdx.y;
    const int b    = blockIdx.z;
    const int e    = g_expert[b];

    // ---- loader addressing (fixed per thread) ----
    const int lrow = tid >> 1;                 // 0..127 (row of A and of B)
    const int lu0  = (tid & 1) * 4;            // first of 4 uint4 slots
    int pix = tile0 + lrow; if (pix > HW_ - 1) pix = HW_ - 1;
    int py = pix / W_, px = pix - py * W_;
    const __half* gA_row = g_wA + ((size_t)(e * OC_ + ocb * 128 + lrow)) * KDIM;
    const size_t xoff = (((size_t)b * HP_ + py) * HP_ + px) * C_;
    const uint32_t sA_row = sbase + lrow * 128;
    const uint32_t sB_row = sbase + 16384 + lrow * 128;
    const int swz = (lrow & 7);

    #define LOAD_CHUNK(CH, D) do {                                              \
        int _t = (CH) >> 2, _q = (CH) & 3;                                      \
        const uint4* _ga = (const uint4*)(gA_row + _t * C_ + _q * 64);          \
        const uint4* _gb = (const uint4*)(g_xh + xoff                           \
                                 + ((_t / 3) * HP_ + (_t % 3)) * C_ + _q * 64); \
        uint32_t _ao = sA_row + (D) * CHUNK_BYTES;                              \
        uint32_t _bo = sB_row + (D) * CHUNK_BYTES;                              \
        _Pragma("unroll")                                                       \
        for (int _u = lu0; _u < lu0 + 4; _u++) {                                \
            cpa16(_ao + (uint32_t)((_u ^ swz) << 4), _ga + _u);                 \
            cpa16(_bo + (uint32_t)((_u ^ swz) << 4), _gb + _u);                 \
        }                                                                        \
    } while (0)

    float acc[4][4][4];
    #pragma unroll
    for (int i = 0; i < 4; i++)
        #pragma unroll
        for (int j = 0; j < 4; j++)
            #pragma unroll
            for (int f = 0; f < 4; f++) acc[i][j][f] = 0.f;

    // ---- ldmatrix lane addressing (fixed per thread) ----
    const int a_r  = (lane & 7) + ((lane >> 3) & 1) * 8;   // row within 16
    const int a_kb = (lane >> 4) * 16;                     // byte offset within k16
    const int b_r  = (lane & 7) + (lane >> 4) * 8;
    const int b_kb = ((lane >> 3) & 1) * 16;

    LOAD_CHUNK(0, 0); cpa_commit();
    LOAD_CHUNK(1, 1); cpa_commit();

    #pragma unroll 1
    for (int ch = 0; ch < NCHUNK; ch++) {
        const int buf = ch % NSTAGE;
        if (ch + 2 < NCHUNK) { LOAD_CHUNK(ch + 2, (ch + 2) % NSTAGE); cpa_commit(); cpa_wait<2>(); }
        else if (ch + 1 < NCHUNK) { cpa_wait<1>(); }
        else { cpa_wait<0>(); }
        __syncthreads();

        const uint32_t sA = sbase + buf * CHUNK_BYTES;
        const uint32_t sB = sA + 16384;
        #pragma unroll
        for (int kk = 0; kk < 4; kk++) {
            uint32_t a[4][4];
            #pragma unroll
            for (int mi = 0; mi < 4; mi++) {
                int row = wm * 64 + mi * 16 + a_r;
                int kb  = kk * 32 + a_kb;
                ldm_x4(a[mi][0], a[mi][1], a[mi][2], a[mi][3],
                       sA + row * 128 + (kb ^ ((row & 7) << 4)));
            }
            #pragma unroll
            for (int pr = 0; pr < 2; pr++) {
                uint32_t bb[4];
                int nrow = wn * 32 + pr * 16 + b_r;
                int kb   = kk * 32 + b_kb;
                ldm_x4(bb[0], bb[1], bb[2], bb[3],
                       sB + nrow * 128 + (kb ^ ((nrow & 7) << 4)));
                #pragma unroll
                for (int mi = 0; mi < 4; mi++) {
                    mma16816(acc[mi][pr * 2],     a[mi], bb);
                    mma16816(acc[mi][pr * 2 + 1], a[mi], bb + 2);
                }
            }
        }
        __syncthreads();
    }

    // ---- epilogue: alpha * acc + bias, direct float2 stores ----
    const float al = alpha[e];
    const int qn = lane & 3, qm = lane >> 2;
    #pragma unroll
    for (int mi = 0; mi < 4; mi++) {
        int oc0 = ocb * 128 + wm * 64 + mi * 16 + qm;
        float bv0 = bias_w[e * OC_ + oc0];
        float bv1 = bias_w[e * OC_ + oc0 + 8];
        #pragma unroll
        for (int ni = 0; ni < 4; ni++) {
            int p = tile0 + wn * 32 + ni * 8 + qn * 2;
            if (p < HW_) {
                float2 v0, v1;
                v0.x = acc[mi][ni][0] * al + bv0;
                v0.y = acc[mi][ni][1] * al + bv0;
                v1.x = acc[mi][ni][2] * al + bv1;
                v1.y = acc[mi][ni][3] * al + bv1;
                *(float2*)(out + ((size_t)(b * OC_ + oc0)) * HW_ + p)     = v0;
                *(float2*)(out + ((size_t)(b * OC_ + oc0 + 8)) * HW_ + p) = v1;
            }
        }
    }
}

// ---------------------------------------------------------------------------
extern "C" void kernel_launch(void* const* d_in, const int* in_sizes, int n_in,
                              void* d_out, int out_size) {
    const float* x      = (const float*)d_in[0];
    const float* w_fc1  = (const float*)d_in[1];
    const float* w_fc2  = (const float*)d_in[2];
    const float* b_fc2  = (const float*)d_in[3];
    const float* alpha  = (const float*)d_in[4];
    const float* weight = (const float*)d_in[5];
    const float* bias_w = (const float*)d_in[6];
    float* out = (float*)d_out;
    float* raw_out = out + SPATIAL_OUT;

    pool_kernel<<<B_ * C_, 256>>>(x);
    attn_kernel<<<B_, 128>>>(w_fc1, w_fc2, b_fc2, raw_out);
    quantw_kernel<<<(K_ * OC_ * C_ * 9 + 255) / 256, 256>>>(weight, alpha);
    zpad_kernel<<<dim3(228, B_), 256>>>();
    xprep_kernel<<<dim3(H_, B_), 256>>>(x);

    cudaFuncSetAttribute(conv_kernel, cudaFuncAttributeMaxDynamicSharedMemorySize, SMEM_CONV);
    conv_kernel<<<dim3(NTILE, 2, B_), 256, SMEM_CONV>>>(bias_w, alpha, out);
}